// round 14
// baseline (speedup 1.0000x reference)
#include <cuda_runtime.h>
#include <math.h>

#define NN 10000
#define EE 320000
#define EP (EE + NN)
#define HH 4
#define CC 128
#define HC 512
#define INC 256
#define EILP 4

// ---------------- scratch ----------------
__device__ float g_xl[NN * HC];
__device__ float g_xr[NN * HC];
__device__ float g_h[NN * CC];
__device__ float g_scr[EP * HH];   // CSR-ordered logit scratch
__device__ float g_m[NN * HH];     // per-node per-head softmax max
__device__ float g_inv[NN * HH];   // per-node per-head 1/denom
__device__ int g_deg[NN];
__device__ int g_off[NN + 1];
__device__ int g_cur[NN];
__device__ int g_src[EP];
__device__ int g_eid[EP];
__device__ int g_dst[EP];
__device__ int g_is64;

// side stream + events (created once; no device memory)
static cudaStream_t s_csr;
static cudaEvent_t ev_fork, ev_join, ev_l1, ev_fin;
static struct StreamInit {
    StreamInit() {
        cudaStreamCreateWithFlags(&s_csr, cudaStreamNonBlocking);
        cudaEventCreateWithFlags(&ev_fork, cudaEventDisableTiming);
        cudaEventCreateWithFlags(&ev_join, cudaEventDisableTiming);
        cudaEventCreateWithFlags(&ev_l1, cudaEventDisableTiming);
        cudaEventCreateWithFlags(&ev_fin, cudaEventDisableTiming);
    }
} s_init;

__device__ __forceinline__ int edge_at(const void* ei, int idx) {
    if (g_is64) return (int)((const long long*)ei)[idx];
    return ((const int*)ei)[idx];
}

// ---------------- dtype probe (parallel) ----------------
__global__ void detect_dtype(const unsigned int* __restrict__ ei) {
    int t = threadIdx.x;
    int bad = (ei[2 * t + 1] != 0u) || (ei[2 * t] >= (unsigned)NN);
    int nbad = __syncthreads_count(bad);
    if (t == 0) g_is64 = (nbad == 0) ? 1 : 0;
}

// ---------------- CSR build ----------------
__global__ void init_deg() {
    int i = blockIdx.x * blockDim.x + threadIdx.x;
    if (i < NN) g_deg[i] = 1;
}

__global__ void count_deg(const void* __restrict__ ei) {
    int e = blockIdx.x * blockDim.x + threadIdx.x;
    if (e < EE) atomicAdd(&g_deg[edge_at(ei, EE + e)], 1);
}

__global__ void scan_off() {
    __shared__ int ss[1024];
    int t = threadIdx.x;
    const int CH = (NN + 1023) / 1024;
    int base = t * CH;
    int s = 0;
    for (int i = 0; i < CH; i++) {
        int idx = base + i;
        if (idx < NN) s += g_deg[idx];
    }
    ss[t] = s;
    __syncthreads();
    for (int o = 1; o < 1024; o <<= 1) {
        int v = (t >= o) ? ss[t - o] : 0;
        __syncthreads();
        ss[t] += v;
        __syncthreads();
    }
    int run = (t == 0) ? 0 : ss[t - 1];
    for (int i = 0; i < CH; i++) {
        int idx = base + i;
        if (idx < NN) {
            g_off[idx] = run;
            g_cur[idx] = run;
            run += g_deg[idx];
        }
    }
    if (t == 1023) g_off[NN] = ss[1023];
}

__global__ void fill_csr(const void* __restrict__ ei) {
    int e = blockIdx.x * blockDim.x + threadIdx.x;
    if (e >= EP) return;
    int s, d;
    if (e < EE) {
        s = edge_at(ei, e);
        d = edge_at(ei, EE + e);
    } else {
        s = e - EE;
        d = s;
    }
    int pos = atomicAdd(&g_cur[d], 1);
    g_src[pos] = s;
    g_eid[pos] = e;
    g_dst[pos] = d;
}

// ---------------- flat alpha finalize (1 thread / edge) ----------------
__global__ void finalize_alpha(float* __restrict__ alpha) {
    int e = blockIdx.x * blockDim.x + threadIdx.x;
    if (e >= EP) return;
    float4 lg = *(const float4*)(g_scr + (size_t)e * HH);
    int d = g_dst[e];
    float4 m4 = *(const float4*)(g_m + (size_t)d * HH);
    float4 i4 = *(const float4*)(g_inv + (size_t)d * HH);
    float4 av;
    av.x = __expf(lg.x - m4.x) * i4.x;
    av.y = __expf(lg.y - m4.y) * i4.y;
    av.z = __expf(lg.z - m4.z) * i4.z;
    av.w = __expf(lg.w - m4.w) * i4.w;
    *(float4*)(alpha + (size_t)g_eid[e] * HH) = av;
}

// ---------------- 3xTF32 tensor-core GEMM ----------------
// merged-z + register prefetch + hi/lo-interleaved smem (LDS.64 fragment loads)
__device__ __forceinline__ unsigned tf32_of(float v) {
    unsigned r;
    asm("cvt.rna.tf32.f32 %0, %1;" : "=r"(r) : "f"(v));
    return r;
}

__device__ __forceinline__ float2 hl_split(float v) {
    unsigned hi = tf32_of(v);
    float hif = __uint_as_float(hi);
    unsigned lo = tf32_of(v - hif);
    return make_float2(hif, __uint_as_float(lo));
}

__device__ __forceinline__ void mma8(float* d, const unsigned* a, const unsigned* b) {
    asm volatile(
        "mma.sync.aligned.m16n8k8.row.col.f32.tf32.tf32.f32 "
        "{%0,%1,%2,%3}, {%4,%5,%6,%7}, {%8,%9}, {%0,%1,%2,%3};"
        : "+f"(d[0]), "+f"(d[1]), "+f"(d[2]), "+f"(d[3])
        : "r"(a[0]), "r"(a[1]), "r"(a[2]), "r"(a[3]), "r"(b[0]), "r"(b[1]));
}

template <int ASEL, int K>
__global__ void __launch_bounds__(256) gemm_tf32(const float* __restrict__ Aext,
                                                 const float* __restrict__ B0,
                                                 const float* __restrict__ B1) {
    const float* A = (ASEL == 0) ? Aext : (const float*)g_h;

    // interleaved {hi,lo} pairs: one LDS.64 fetches both
    __shared__ float2 As_hl[16][132];
    __shared__ float2 Bs_hl[2][16][68];

    int t = threadIdx.x;
    int lane = t & 31, wid = t >> 5;
    int wm = wid & 3, wn = wid >> 2;
    int tg = lane >> 2, tq = lane & 3;
    int bm = blockIdx.y * 128, bn = blockIdx.x * 64;

    float acc[2][2][4][4];
#pragma unroll
    for (int z = 0; z < 2; z++)
#pragma unroll
        for (int mt = 0; mt < 2; mt++)
#pragma unroll
            for (int nt = 0; nt < 4; nt++)
#pragma unroll
                for (int j = 0; j < 4; j++) acc[z][mt][nt][j] = 0.f;

    const int ar0 = t >> 2, ac0 = (t & 3) * 4;
    const int ar1 = (t + 256) >> 2;
    const int br = t >> 4, bc = (t & 15) * 4;

    float4 avA0, avA1, bv0, bv1;
    {
        avA0 = make_float4(0.f, 0.f, 0.f, 0.f);
        avA1 = make_float4(0.f, 0.f, 0.f, 0.f);
        if (bm + ar0 < NN) avA0 = *(const float4*)(A + (size_t)(bm + ar0) * K + ac0);
        if (bm + ar1 < NN) avA1 = *(const float4*)(A + (size_t)(bm + ar1) * K + ac0);
        bv0 = *(const float4*)(B0 + (size_t)br * HC + bn + bc);
        bv1 = *(const float4*)(B1 + (size_t)br * HC + bn + bc);
    }

    for (int k0 = 0; k0 < K; k0 += 16) {
        {
            float vv0[4] = {avA0.x, avA0.y, avA0.z, avA0.w};
            float vv1[4] = {avA1.x, avA1.y, avA1.z, avA1.w};
#pragma unroll
            for (int j = 0; j < 4; j++) {
                As_hl[ac0 + j][ar0] = hl_split(vv0[j]);
                As_hl[ac0 + j][ar1] = hl_split(vv1[j]);
            }
            float bb0[4] = {bv0.x, bv0.y, bv0.z, bv0.w};
            float bb1[4] = {bv1.x, bv1.y, bv1.z, bv1.w};
#pragma unroll
            for (int j = 0; j < 4; j++) {
                Bs_hl[0][br][bc + j] = hl_split(bb0[j]);
                Bs_hl[1][br][bc + j] = hl_split(bb1[j]);
            }
        }
        __syncthreads();

        if (k0 + 16 < K) {
            int kn = k0 + 16;
            avA0 = make_float4(0.f, 0.f, 0.f, 0.f);
            avA1 = make_float4(0.f, 0.f, 0.f, 0.f);
            if (bm + ar0 < NN) avA0 = *(const float4*)(A + (size_t)(bm + ar0) * K + kn + ac0);
            if (bm + ar1 < NN) avA1 = *(const float4*)(A + (size_t)(bm + ar1) * K + kn + ac0);
            bv0 = *(const float4*)(B0 + (size_t)(kn + br) * HC + bn + bc);
            bv1 = *(const float4*)(B1 + (size_t)(kn + br) * HC + bn + bc);
        }

#pragma unroll
        for (int ks = 0; ks < 2; ks++) {
            int kk = ks * 8;
            unsigned ah[2][4], al[2][4];
#pragma unroll
            for (int mt = 0; mt < 2; mt++) {
                int rb = wm * 32 + mt * 16;
                float2 v00 = As_hl[kk + tq][rb + tg];
                float2 v01 = As_hl[kk + tq][rb + tg + 8];
                float2 v10 = As_hl[kk + tq + 4][rb + tg];
                float2 v11 = As_hl[kk + tq + 4][rb + tg + 8];
                ah[mt][0] = __float_as_uint(v00.x);
                ah[mt][1] = __float_as_uint(v01.x);
                ah[mt][2] = __float_as_uint(v10.x);
                ah[mt][3] = __float_as_uint(v11.x);
                al[mt][0] = __float_as_uint(v00.y);
                al[mt][1] = __float_as_uint(v01.y);
                al[mt][2] = __float_as_uint(v10.y);
                al[mt][3] = __float_as_uint(v11.y);
            }
#pragma unroll
            for (int z = 0; z < 2; z++) {
#pragma unroll
                for (int nt = 0; nt < 4; nt++) {
                    int cb = wn * 32 + nt * 8;
                    float2 w0 = Bs_hl[z][kk + tq][cb + tg];
                    float2 w1 = Bs_hl[z][kk + tq + 4][cb + tg];
                    unsigned bh[2], bl[2];
                    bh[0] = __float_as_uint(w0.x);
                    bh[1] = __float_as_uint(w1.x);
                    bl[0] = __float_as_uint(w0.y);
                    bl[1] = __float_as_uint(w1.y);
#pragma unroll
                    for (int mt = 0; mt < 2; mt++) {
                        mma8(acc[z][mt][nt], ah[mt], bh);
                        mma8(acc[z][mt][nt], ah[mt], bl);
                        mma8(acc[z][mt][nt], al[mt], bh);
                    }
                }
            }
        }
        __syncthreads();
    }

#pragma unroll
    for (int z = 0; z < 2; z++) {
        float* C = z ? g_xr : g_xl;
#pragma unroll
        for (int mt = 0; mt < 2; mt++)
#pragma unroll
            for (int nt = 0; nt < 4; nt++) {
                int row = bm + wm * 32 + mt * 16 + tg;
                int col = bn + wn * 32 + nt * 8 + 2 * tq;
                if (row < NN)
                    *(float2*)(C + (size_t)row * HC + col) =
                        make_float2(acc[z][mt][nt][0], acc[z][mt][nt][1]);
                if (row + 8 < NN)
                    *(float2*)(C + (size_t)(row + 8) * HC + col) =
                        make_float2(acc[z][mt][nt][2], acc[z][mt][nt][3]);
            }
    }
}

// ---------------- edge / softmax / aggregate kernel ----------------
// block = dst node, warp = head, online softmax, 4-edge ILP batching.
template <int LAYER, int FIN>
__global__ void __launch_bounds__(128) edge_attn(
    const float* __restrict__ att, const float* __restrict__ bias,
    const float* __restrict__ bng, const float* __restrict__ bnb,
    const float* __restrict__ bnm, const float* __restrict__ bnv,
    const float* __restrict__ Wlin, const float* __restrict__ blin,
    float* __restrict__ alpha, float* __restrict__ nodeout) {
    const float* xl = (const float*)g_xl;
    const float* xr = (const float*)g_xr;
    int i = blockIdx.x, t = threadIdx.x;
    int h = t >> 5, lane = t & 31;
    int start = g_off[i], end = g_off[i + 1];
    int col = h * CC + lane * 4;

    const float4 xr4 = *(const float4*)(xr + (size_t)i * HC + col);
    const float4 a4 = *(const float4*)(att + col);

    float m = -3.4e38f, denom = 0.f;
    float4 acc = make_float4(0.f, 0.f, 0.f, 0.f);

    int e = start;
    int deg = end - start;
    int nfull = deg & ~(EILP - 1);

    for (; e < start + nfull; e += EILP) {
        int s[EILP];
        float4 xv[EILP];
#pragma unroll
        for (int j = 0; j < EILP; j++) s[j] = g_src[e + j];
#pragma unroll
        for (int j = 0; j < EILP; j++)
            xv[j] = *(const float4*)(xl + (size_t)s[j] * HC + col);

        float p[EILP];
#pragma unroll
        for (int j = 0; j < EILP; j++) {
            float t0 = xv[j].x + xr4.x;
            float t1 = xv[j].y + xr4.y;
            float t2 = xv[j].z + xr4.z;
            float t3 = xv[j].w + xr4.w;
            t0 = t0 > 0.f ? t0 : 0.2f * t0;
            t1 = t1 > 0.f ? t1 : 0.2f * t1;
            t2 = t2 > 0.f ? t2 : 0.2f * t2;
            t3 = t3 > 0.f ? t3 : 0.2f * t3;
            p[j] = t0 * a4.x + t1 * a4.y + t2 * a4.z + t3 * a4.w;
        }
#pragma unroll
        for (int o = 16; o; o >>= 1) {
#pragma unroll
            for (int j = 0; j < EILP; j++)
                p[j] += __shfl_xor_sync(0xffffffffu, p[j], o);
        }
#pragma unroll
        for (int j = 0; j < EILP; j++) {
            if (lane == 0) g_scr[(e + j) * HH + h] = p[j];
            if (p[j] > m) {
                float sc = __expf(m - p[j]);
                denom *= sc;
                acc.x *= sc; acc.y *= sc; acc.z *= sc; acc.w *= sc;
                m = p[j];
            }
            float ex = __expf(p[j] - m);
            denom += ex;
            acc.x += ex * xv[j].x;
            acc.y += ex * xv[j].y;
            acc.z += ex * xv[j].z;
            acc.w += ex * xv[j].w;
        }
    }
    for (; e < end; e++) {
        int s = g_src[e];
        float4 xv = *(const float4*)(xl + (size_t)s * HC + col);
        float t0 = xv.x + xr4.x;
        float t1 = xv.y + xr4.y;
        float t2 = xv.z + xr4.z;
        float t3 = xv.w + xr4.w;
        t0 = t0 > 0.f ? t0 : 0.2f * t0;
        t1 = t1 > 0.f ? t1 : 0.2f * t1;
        t2 = t2 > 0.f ? t2 : 0.2f * t2;
        t3 = t3 > 0.f ? t3 : 0.2f * t3;
        float p = t0 * a4.x + t1 * a4.y + t2 * a4.z + t3 * a4.w;
#pragma unroll
        for (int o = 16; o; o >>= 1) p += __shfl_xor_sync(0xffffffffu, p, o);
        if (lane == 0) g_scr[e * HH + h] = p;
        if (p > m) {
            float sc = __expf(m - p);
            denom *= sc;
            acc.x *= sc; acc.y *= sc; acc.z *= sc; acc.w *= sc;
            m = p;
        }
        float ex = __expf(p - m);
        denom += ex;
        acc.x += ex * xv.x;
        acc.y += ex * xv.y;
        acc.z += ex * xv.z;
        acc.w += ex * xv.w;
    }
    float inv = 1.f / (denom + 1e-16f);

    __shared__ float red[HC];
    __shared__ float sm_m[HH], sm_inv[HH];
    red[col + 0] = acc.x * inv;
    red[col + 1] = acc.y * inv;
    red[col + 2] = acc.z * inv;
    red[col + 3] = acc.w * inv;
    if (lane == 0) {
        if (FIN) {
            sm_m[h] = m;
            sm_inv[h] = inv;
        } else {
            g_m[i * HH + h] = m;
            g_inv[i * HH + h] = inv;
        }
    }
    __syncthreads();

    if (FIN) {
        for (int ee = start + t; ee < end; ee += 128) {
            float4 lg = *(const float4*)(g_scr + ee * HH);
            float4 av;
            av.x = __expf(lg.x - sm_m[0]) * sm_inv[0];
            av.y = __expf(lg.y - sm_m[1]) * sm_inv[1];
            av.z = __expf(lg.z - sm_m[2]) * sm_inv[2];
            av.w = __expf(lg.w - sm_m[3]) * sm_inv[3];
            *(float4*)(alpha + (size_t)g_eid[ee] * HH) = av;
        }
    }

    // combine heads (mean), bias, BN, ReLU
    float sum = (red[t] + red[CC + t] + red[2 * CC + t] + red[3 * CC + t]) * 0.25f + bias[t];
    float scale = bng[t] * rsqrtf(bnv[t] + 1e-5f);
    float y = (sum - bnm[t]) * scale + bnb[t];
    y = fmaxf(y, 0.f);

    if (LAYER == 1) {
        g_h[(size_t)i * CC + t] = y;
    } else {
        __shared__ float rr[CC];
        rr[t] = y * Wlin[t];
        __syncthreads();
#pragma unroll
        for (int o = 64; o; o >>= 1) {
            if (t < o) rr[t] += rr[t + o];
            __syncthreads();
        }
        if (t == 0) {
            float z = fmaxf(rr[0] + blin[0], 0.f);
            nodeout[i] = 1.f / (1.f + __expf(-z));
        }
    }
}

// ---------------- launch ----------------
extern "C" void kernel_launch(void* const* d_in, const int* in_sizes, int n_in,
                              void* d_out, int out_size) {
    const float* x = (const float*)d_in[0];
    const void* ei = d_in[1];
    const float* Wl1 = (const float*)d_in[2];
    const float* Wr1 = (const float*)d_in[3];
    const float* att1 = (const float*)d_in[4];
    const float* b1 = (const float*)d_in[5];
    const float* Wl2 = (const float*)d_in[6];
    const float* Wr2 = (const float*)d_in[7];
    const float* att2 = (const float*)d_in[8];
    const float* b2 = (const float*)d_in[9];
    const float* g1 = (const float*)d_in[10];
    const float* be1 = (const float*)d_in[11];
    const float* m1 = (const float*)d_in[12];
    const float* v1 = (const float*)d_in[13];
    const float* g2 = (const float*)d_in[14];
    const float* be2 = (const float*)d_in[15];
    const float* m2 = (const float*)d_in[16];
    const float* v2 = (const float*)d_in[17];
    const float* Wlin = (const float*)d_in[18];
    const float* blin = (const float*)d_in[19];

    float* out = (float*)d_out;
    float* alpha1 = out + NN;
    float* alpha2 = alpha1 + (size_t)EP * HH;

    // fork: CSR build on side stream, overlapped with layer-1 GEMM
    cudaEventRecord(ev_fork, 0);
    cudaStreamWaitEvent(s_csr, ev_fork, 0);
    detect_dtype<<<1, 128, 0, s_csr>>>((const unsigned int*)ei);
    init_deg<<<(NN + 255) / 256, 256, 0, s_csr>>>();
    count_deg<<<(EE + 255) / 256, 256, 0, s_csr>>>(ei);

    dim3 gg(HC / 64, (NN + 127) / 128);
    gemm_tf32<0, INC><<<gg, 256>>>(x, Wl1, Wr1);

    scan_off<<<1, 1024, 0, s_csr>>>();
    fill_csr<<<(EP + 255) / 256, 256, 0, s_csr>>>(ei);
    cudaEventRecord(ev_join, s_csr);

    // join: edge_attn needs both GEMM output (main) and CSR (side)
    cudaStreamWaitEvent(0, ev_join, 0);
    edge_attn<1, 0><<<NN, 128>>>(att1, b1, g1, be1, m1, v1,
                                 nullptr, nullptr, alpha1, nullptr);
    cudaEventRecord(ev_l1, 0);

    // layer-1 alpha finalize on side stream, overlapped with GEMM2
    cudaStreamWaitEvent(s_csr, ev_l1, 0);
    finalize_alpha<<<(EP + 255) / 256, 256, 0, s_csr>>>(alpha1);
    cudaEventRecord(ev_fin, s_csr);

    gemm_tf32<1, CC><<<gg, 256>>>(nullptr, Wl2, Wr2);

    // edge_attn2 rewrites g_scr -> must wait for finalize_alpha to drain it
    cudaStreamWaitEvent(0, ev_fin, 0);
    edge_attn<2, 1><<<NN, 128>>>(att2, b2, g2, be2, m2, v2,
                                 Wlin, blin, alpha2, out);
}

// round 16
// speedup vs baseline: 1.0957x; 1.0957x over previous
#include <cuda_runtime.h>
#include <math.h>

#define NN 10000
#define EE 320000
#define EP (EE + NN)
#define HH 4
#define CC 128
#define HC 512
#define INC 256
#define EILP 4

// smem strides chosen ≡ 8 (mod 32 banks) -> conflict-free fragment LDS
#define ASTR 136
#define BSTR 72

// ---------------- scratch ----------------
__device__ float g_xl[NN * HC];
__device__ float g_xr[NN * HC];
__device__ float g_h[NN * CC];
__device__ float g_scr[EP * HH];
__device__ float g_m[NN * HH];
__device__ float g_inv[NN * HH];
__device__ int g_deg[NN];
__device__ int g_off[NN + 1];
__device__ int g_cur[NN];
__device__ int g_src[EP];
__device__ int g_eid[EP];
__device__ int g_dst[EP];
__device__ int g_is64;

static cudaStream_t s_csr;
static cudaEvent_t ev_fork, ev_join, ev_l1, ev_fin;
static struct StreamInit {
    StreamInit() {
        cudaStreamCreateWithFlags(&s_csr, cudaStreamNonBlocking);
        cudaEventCreateWithFlags(&ev_fork, cudaEventDisableTiming);
        cudaEventCreateWithFlags(&ev_join, cudaEventDisableTiming);
        cudaEventCreateWithFlags(&ev_l1, cudaEventDisableTiming);
        cudaEventCreateWithFlags(&ev_fin, cudaEventDisableTiming);
    }
} s_init;

__device__ __forceinline__ int edge_at(const void* ei, int idx) {
    if (g_is64) return (int)((const long long*)ei)[idx];
    return ((const int*)ei)[idx];
}

__global__ void detect_dtype(const unsigned int* __restrict__ ei) {
    int t = threadIdx.x;
    int bad = (ei[2 * t + 1] != 0u) || (ei[2 * t] >= (unsigned)NN);
    int nbad = __syncthreads_count(bad);
    if (t == 0) g_is64 = (nbad == 0) ? 1 : 0;
}

__global__ void init_deg() {
    int i = blockIdx.x * blockDim.x + threadIdx.x;
    if (i < NN) g_deg[i] = 1;
}

__global__ void count_deg(const void* __restrict__ ei) {
    int e = blockIdx.x * blockDim.x + threadIdx.x;
    if (e < EE) atomicAdd(&g_deg[edge_at(ei, EE + e)], 1);
}

__global__ void scan_off() {
    __shared__ int ss[1024];
    int t = threadIdx.x;
    const int CH = (NN + 1023) / 1024;
    int base = t * CH;
    int s = 0;
    for (int i = 0; i < CH; i++) {
        int idx = base + i;
        if (idx < NN) s += g_deg[idx];
    }
    ss[t] = s;
    __syncthreads();
    for (int o = 1; o < 1024; o <<= 1) {
        int v = (t >= o) ? ss[t - o] : 0;
        __syncthreads();
        ss[t] += v;
        __syncthreads();
    }
    int run = (t == 0) ? 0 : ss[t - 1];
    for (int i = 0; i < CH; i++) {
        int idx = base + i;
        if (idx < NN) {
            g_off[idx] = run;
            g_cur[idx] = run;
            run += g_deg[idx];
        }
    }
    if (t == 1023) g_off[NN] = ss[1023];
}

__global__ void fill_csr(const void* __restrict__ ei) {
    int e = blockIdx.x * blockDim.x + threadIdx.x;
    if (e >= EP) return;
    int s, d;
    if (e < EE) {
        s = edge_at(ei, e);
        d = edge_at(ei, EE + e);
    } else {
        s = e - EE;
        d = s;
    }
    int pos = atomicAdd(&g_cur[d], 1);
    g_src[pos] = s;
    g_eid[pos] = e;
    g_dst[pos] = d;
}

__global__ void finalize_alpha(float* __restrict__ alpha) {
    int e = blockIdx.x * blockDim.x + threadIdx.x;
    if (e >= EP) return;
    float4 lg = *(const float4*)(g_scr + (size_t)e * HH);
    int d = g_dst[e];
    float4 m4 = *(const float4*)(g_m + (size_t)d * HH);
    float4 i4 = *(const float4*)(g_inv + (size_t)d * HH);
    float4 av;
    av.x = __expf(lg.x - m4.x) * i4.x;
    av.y = __expf(lg.y - m4.y) * i4.y;
    av.z = __expf(lg.z - m4.z) * i4.z;
    av.w = __expf(lg.w - m4.w) * i4.w;
    *(float4*)(alpha + (size_t)g_eid[e] * HH) = av;
}

// ---------------- 3xTF32 tensor-core GEMM ----------------
__device__ __forceinline__ unsigned tf32_of(float v) {
    unsigned r;
    asm("cvt.rna.tf32.f32 %0, %1;" : "=r"(r) : "f"(v));
    return r;
}

__device__ __forceinline__ void mma8(float* d, const unsigned* a, const unsigned* b) {
    asm volatile(
        "mma.sync.aligned.m16n8k8.row.col.f32.tf32.tf32.f32 "
        "{%0,%1,%2,%3}, {%4,%5,%6,%7}, {%8,%9}, {%0,%1,%2,%3};"
        : "+f"(d[0]), "+f"(d[1]), "+f"(d[2]), "+f"(d[3])
        : "r"(a[0]), "r"(a[1]), "r"(a[2]), "r"(a[3]), "r"(b[0]), "r"(b[1]));
}

template <int ASEL, int K>
__global__ void __launch_bounds__(256) gemm_tf32(const float* __restrict__ Aext,
                                                 const float* __restrict__ B0,
                                                 const float* __restrict__ B1) {
    const float* A = (ASEL == 0) ? Aext : (const float*)g_h;

    __shared__ float As_hi[16][ASTR], As_lo[16][ASTR];
    __shared__ float Bs_hi[2][16][BSTR], Bs_lo[2][16][BSTR];

    int t = threadIdx.x;
    int lane = t & 31, wid = t >> 5;
    int wm = wid & 3, wn = wid >> 2;
    int tg = lane >> 2, tq = lane & 3;
    int bm = blockIdx.y * 128, bn = blockIdx.x * 64;

    float acc[2][2][4][4];
#pragma unroll
    for (int z = 0; z < 2; z++)
#pragma unroll
        for (int mt = 0; mt < 2; mt++)
#pragma unroll
            for (int nt = 0; nt < 4; nt++)
#pragma unroll
                for (int j = 0; j < 4; j++) acc[z][mt][nt][j] = 0.f;

    const int ar0 = t >> 2, ac0 = (t & 3) * 4;
    const int ar1 = (t + 256) >> 2;
    const int br = t >> 4, bc = (t & 15) * 4;

    float4 avA0, avA1, bv0, bv1;
    {
        avA0 = make_float4(0.f, 0.f, 0.f, 0.f);
        avA1 = make_float4(0.f, 0.f, 0.f, 0.f);
        if (bm + ar0 < NN) avA0 = *(const float4*)(A + (size_t)(bm + ar0) * K + ac0);
        if (bm + ar1 < NN) avA1 = *(const float4*)(A + (size_t)(bm + ar1) * K + ac0);
        bv0 = *(const float4*)(B0 + (size_t)br * HC + bn + bc);
        bv1 = *(const float4*)(B1 + (size_t)br * HC + bn + bc);
    }

    for (int k0 = 0; k0 < K; k0 += 16) {
        {
            float vv0[4] = {avA0.x, avA0.y, avA0.z, avA0.w};
            float vv1[4] = {avA1.x, avA1.y, avA1.z, avA1.w};
#pragma unroll
            for (int j = 0; j < 4; j++) {
                unsigned hi = tf32_of(vv0[j]);
                float hif = __uint_as_float(hi);
                unsigned lo = tf32_of(vv0[j] - hif);
                As_hi[ac0 + j][ar0] = hif;
                As_lo[ac0 + j][ar0] = __uint_as_float(lo);
                hi = tf32_of(vv1[j]);
                hif = __uint_as_float(hi);
                lo = tf32_of(vv1[j] - hif);
                As_hi[ac0 + j][ar1] = hif;
                As_lo[ac0 + j][ar1] = __uint_as_float(lo);
            }
            float bb0[4] = {bv0.x, bv0.y, bv0.z, bv0.w};
            float bb1[4] = {bv1.x, bv1.y, bv1.z, bv1.w};
#pragma unroll
            for (int j = 0; j < 4; j++) {
                unsigned hi = tf32_of(bb0[j]);
                float hif = __uint_as_float(hi);
                unsigned lo = tf32_of(bb0[j] - hif);
                Bs_hi[0][br][bc + j] = hif;
                Bs_lo[0][br][bc + j] = __uint_as_float(lo);
                hi = tf32_of(bb1[j]);
                hif = __uint_as_float(hi);
                lo = tf32_of(bb1[j] - hif);
                Bs_hi[1][br][bc + j] = hif;
                Bs_lo[1][br][bc + j] = __uint_as_float(lo);
            }
        }
        __syncthreads();

        if (k0 + 16 < K) {
            int kn = k0 + 16;
            avA0 = make_float4(0.f, 0.f, 0.f, 0.f);
            avA1 = make_float4(0.f, 0.f, 0.f, 0.f);
            if (bm + ar0 < NN) avA0 = *(const float4*)(A + (size_t)(bm + ar0) * K + kn + ac0);
            if (bm + ar1 < NN) avA1 = *(const float4*)(A + (size_t)(bm + ar1) * K + kn + ac0);
            bv0 = *(const float4*)(B0 + (size_t)(kn + br) * HC + bn + bc);
            bv1 = *(const float4*)(B1 + (size_t)(kn + br) * HC + bn + bc);
        }

#pragma unroll
        for (int ks = 0; ks < 2; ks++) {
            int kk = ks * 8;
            unsigned ah[2][4], al[2][4];
#pragma unroll
            for (int mt = 0; mt < 2; mt++) {
                int rb = wm * 32 + mt * 16;
                ah[mt][0] = __float_as_uint(As_hi[kk + tq][rb + tg]);
                ah[mt][1] = __float_as_uint(As_hi[kk + tq][rb + tg + 8]);
                ah[mt][2] = __float_as_uint(As_hi[kk + tq + 4][rb + tg]);
                ah[mt][3] = __float_as_uint(As_hi[kk + tq + 4][rb + tg + 8]);
                al[mt][0] = __float_as_uint(As_lo[kk + tq][rb + tg]);
                al[mt][1] = __float_as_uint(As_lo[kk + tq][rb + tg + 8]);
                al[mt][2] = __float_as_uint(As_lo[kk + tq + 4][rb + tg]);
                al[mt][3] = __float_as_uint(As_lo[kk + tq + 4][rb + tg + 8]);
            }
#pragma unroll
            for (int z = 0; z < 2; z++) {
#pragma unroll
                for (int nt = 0; nt < 4; nt++) {
                    int cb = wn * 32 + nt * 8;
                    unsigned bh[2], bl[2];
                    bh[0] = __float_as_uint(Bs_hi[z][kk + tq][cb + tg]);
                    bh[1] = __float_as_uint(Bs_hi[z][kk + tq + 4][cb + tg]);
                    bl[0] = __float_as_uint(Bs_lo[z][kk + tq][cb + tg]);
                    bl[1] = __float_as_uint(Bs_lo[z][kk + tq + 4][cb + tg]);
#pragma unroll
                    for (int mt = 0; mt < 2; mt++) {
                        mma8(acc[z][mt][nt], ah[mt], bh);
                        mma8(acc[z][mt][nt], ah[mt], bl);
                        mma8(acc[z][mt][nt], al[mt], bh);
                    }
                }
            }
        }
        __syncthreads();
    }

#pragma unroll
    for (int z = 0; z < 2; z++) {
        float* C = z ? g_xr : g_xl;
#pragma unroll
        for (int mt = 0; mt < 2; mt++)
#pragma unroll
            for (int nt = 0; nt < 4; nt++) {
                int row = bm + wm * 32 + mt * 16 + tg;
                int col = bn + wn * 32 + nt * 8 + 2 * tq;
                if (row < NN)
                    *(float2*)(C + (size_t)row * HC + col) =
                        make_float2(acc[z][mt][nt][0], acc[z][mt][nt][1]);
                if (row + 8 < NN)
                    *(float2*)(C + (size_t)(row + 8) * HC + col) =
                        make_float2(acc[z][mt][nt][2], acc[z][mt][nt][3]);
            }
    }
}

// ---------------- edge / softmax / aggregate kernel ----------------
template <int LAYER, int FIN>
__global__ void __launch_bounds__(128) edge_attn(
    const float* __restrict__ att, const float* __restrict__ bias,
    const float* __restrict__ bng, const float* __restrict__ bnb,
    const float* __restrict__ bnm, const float* __restrict__ bnv,
    const float* __restrict__ Wlin, const float* __restrict__ blin,
    float* __restrict__ alpha, float* __restrict__ nodeout) {
    const float* xl = (const float*)g_xl;
    const float* xr = (const float*)g_xr;
    int i = blockIdx.x, t = threadIdx.x;
    int h = t >> 5, lane = t & 31;
    int start = g_off[i], end = g_off[i + 1];
    int col = h * CC + lane * 4;

    const float4 xr4 = *(const float4*)(xr + (size_t)i * HC + col);
    const float4 a4 = *(const float4*)(att + col);

    float m = -3.4e38f, denom = 0.f;
    float4 acc = make_float4(0.f, 0.f, 0.f, 0.f);

    int e = start;
    int deg = end - start;
    int nfull = deg & ~(EILP - 1);

    for (; e < start + nfull; e += EILP) {
        int s[EILP];
        float4 xv[EILP];
#pragma unroll
        for (int j = 0; j < EILP; j++) s[j] = g_src[e + j];
#pragma unroll
        for (int j = 0; j < EILP; j++)
            xv[j] = *(const float4*)(xl + (size_t)s[j] * HC + col);

        float p[EILP];
#pragma unroll
        for (int j = 0; j < EILP; j++) {
            float t0 = xv[j].x + xr4.x;
            float t1 = xv[j].y + xr4.y;
            float t2 = xv[j].z + xr4.z;
            float t3 = xv[j].w + xr4.w;
            t0 = t0 > 0.f ? t0 : 0.2f * t0;
            t1 = t1 > 0.f ? t1 : 0.2f * t1;
            t2 = t2 > 0.f ? t2 : 0.2f * t2;
            t3 = t3 > 0.f ? t3 : 0.2f * t3;
            p[j] = t0 * a4.x + t1 * a4.y + t2 * a4.z + t3 * a4.w;
        }
#pragma unroll
        for (int o = 16; o; o >>= 1) {
#pragma unroll
            for (int j = 0; j < EILP; j++)
                p[j] += __shfl_xor_sync(0xffffffffu, p[j], o);
        }
#pragma unroll
        for (int j = 0; j < EILP; j++) {
            if (lane == 0) g_scr[(e + j) * HH + h] = p[j];
            if (p[j] > m) {
                float sc = __expf(m - p[j]);
                denom *= sc;
                acc.x *= sc; acc.y *= sc; acc.z *= sc; acc.w *= sc;
                m = p[j];
            }
            float ex = __expf(p[j] - m);
            denom += ex;
            acc.x += ex * xv[j].x;
            acc.y += ex * xv[j].y;
            acc.z += ex * xv[j].z;
            acc.w += ex * xv[j].w;
        }
    }
    for (; e < end; e++) {
        int s = g_src[e];
        float4 xv = *(const float4*)(xl + (size_t)s * HC + col);
        float t0 = xv.x + xr4.x;
        float t1 = xv.y + xr4.y;
        float t2 = xv.z + xr4.z;
        float t3 = xv.w + xr4.w;
        t0 = t0 > 0.f ? t0 : 0.2f * t0;
        t1 = t1 > 0.f ? t1 : 0.2f * t1;
        t2 = t2 > 0.f ? t2 : 0.2f * t2;
        t3 = t3 > 0.f ? t3 : 0.2f * t3;
        float p = t0 * a4.x + t1 * a4.y + t2 * a4.z + t3 * a4.w;
#pragma unroll
        for (int o = 16; o; o >>= 1) p += __shfl_xor_sync(0xffffffffu, p, o);
        if (lane == 0) g_scr[e * HH + h] = p;
        if (p > m) {
            float sc = __expf(m - p);
            denom *= sc;
            acc.x *= sc; acc.y *= sc; acc.z *= sc; acc.w *= sc;
            m = p;
        }
        float ex = __expf(p - m);
        denom += ex;
        acc.x += ex * xv.x;
        acc.y += ex * xv.y;
        acc.z += ex * xv.z;
        acc.w += ex * xv.w;
    }
    float inv = 1.f / (denom + 1e-16f);

    __shared__ float red[HC];
    __shared__ float sm_m[HH], sm_inv[HH];
    red[col + 0] = acc.x * inv;
    red[col + 1] = acc.y * inv;
    red[col + 2] = acc.z * inv;
    red[col + 3] = acc.w * inv;
    if (lane == 0) {
        if (FIN) {
            sm_m[h] = m;
            sm_inv[h] = inv;
        } else {
            g_m[i * HH + h] = m;
            g_inv[i * HH + h] = inv;
        }
    }
    __syncthreads();

    if (FIN) {
        for (int ee = start + t; ee < end; ee += 128) {
            float4 lg = *(const float4*)(g_scr + ee * HH);
            float4 av;
            av.x = __expf(lg.x - sm_m[0]) * sm_inv[0];
            av.y = __expf(lg.y - sm_m[1]) * sm_inv[1];
            av.z = __expf(lg.z - sm_m[2]) * sm_inv[2];
            av.w = __expf(lg.w - sm_m[3]) * sm_inv[3];
            *(float4*)(alpha + (size_t)g_eid[ee] * HH) = av;
        }
    }

    float sum = (red[t] + red[CC + t] + red[2 * CC + t] + red[3 * CC + t]) * 0.25f + bias[t];
    float scale = bng[t] * rsqrtf(bnv[t] + 1e-5f);
    float y = (sum - bnm[t]) * scale + bnb[t];
    y = fmaxf(y, 0.f);

    if (LAYER == 1) {
        g_h[(size_t)i * CC + t] = y;
    } else {
        __shared__ float rr[CC];
        rr[t] = y * Wlin[t];
        __syncthreads();
#pragma unroll
        for (int o = 64; o; o >>= 1) {
            if (t < o) rr[t] += rr[t + o];
            __syncthreads();
        }
        if (t == 0) {
            float z = fmaxf(rr[0] + blin[0], 0.f);
            nodeout[i] = 1.f / (1.f + __expf(-z));
        }
    }
}

// ---------------- launch ----------------
extern "C" void kernel_launch(void* const* d_in, const int* in_sizes, int n_in,
                              void* d_out, int out_size) {
    const float* x = (const float*)d_in[0];
    const void* ei = d_in[1];
    const float* Wl1 = (const float*)d_in[2];
    const float* Wr1 = (const float*)d_in[3];
    const float* att1 = (const float*)d_in[4];
    const float* b1 = (const float*)d_in[5];
    const float* Wl2 = (const float*)d_in[6];
    const float* Wr2 = (const float*)d_in[7];
    const float* att2 = (const float*)d_in[8];
    const float* b2 = (const float*)d_in[9];
    const float* g1 = (const float*)d_in[10];
    const float* be1 = (const float*)d_in[11];
    const float* m1 = (const float*)d_in[12];
    const float* v1 = (const float*)d_in[13];
    const float* g2 = (const float*)d_in[14];
    const float* be2 = (const float*)d_in[15];
    const float* m2 = (const float*)d_in[16];
    const float* v2 = (const float*)d_in[17];
    const float* Wlin = (const float*)d_in[18];
    const float* blin = (const float*)d_in[19];

    float* out = (float*)d_out;
    float* alpha1 = out + NN;
    float* alpha2 = alpha1 + (size_t)EP * HH;

    cudaEventRecord(ev_fork, 0);
    cudaStreamWaitEvent(s_csr, ev_fork, 0);
    detect_dtype<<<1, 128, 0, s_csr>>>((const unsigned int*)ei);
    init_deg<<<(NN + 255) / 256, 256, 0, s_csr>>>();
    count_deg<<<(EE + 255) / 256, 256, 0, s_csr>>>(ei);

    dim3 gg(HC / 64, (NN + 127) / 128);
    gemm_tf32<0, INC><<<gg, 256>>>(x, Wl1, Wr1);

    scan_off<<<1, 1024, 0, s_csr>>>();
    fill_csr<<<(EP + 255) / 256, 256, 0, s_csr>>>(ei);
    cudaEventRecord(ev_join, s_csr);

    cudaStreamWaitEvent(0, ev_join, 0);
    edge_attn<1, 0><<<NN, 128>>>(att1, b1, g1, be1, m1, v1,
                                 nullptr, nullptr, alpha1, nullptr);
    cudaEventRecord(ev_l1, 0);

    cudaStreamWaitEvent(s_csr, ev_l1, 0);
    finalize_alpha<<<(EP + 255) / 256, 256, 0, s_csr>>>(alpha1);
    cudaEventRecord(ev_fin, s_csr);

    gemm_tf32<1, CC><<<gg, 256>>>(nullptr, Wl2, Wr2);

    cudaStreamWaitEvent(0, ev_fin, 0);
    edge_attn<2, 1><<<NN, 128>>>(att2, b2, g2, be2, m2, v2,
                                 Wlin, blin, alpha2, out);
}

// round 17
// speedup vs baseline: 1.1018x; 1.0057x over previous
#include <cuda_runtime.h>
#include <math.h>

#define NN 10000
#define EE 320000
#define EP (EE + NN)
#define HH 4
#define CC 128
#define HC 512
#define INC 256
#define EILP 4

// smem strides chosen ≡ 8 (mod 32 banks) -> conflict-free fragment LDS
#define ASTR 136
#define BSTR 72

// dynamic smem: double-buffered A(hi,lo) + B(2z, hi,lo)
#define A_BUF (16 * ASTR)          // floats per A buffer per half
#define B_BUF (2 * 16 * BSTR)      // floats per B buffer per half (z-major)
#define SMEM_FLOATS (2 * A_BUF * 2 + 2 * B_BUF * 2)
#define SMEM_BYTES (SMEM_FLOATS * 4)

// ---------------- scratch ----------------
__device__ float g_xl[NN * HC];
__device__ float g_xr[NN * HC];
__device__ float g_h[NN * CC];
__device__ float g_scr[EP * HH];
__device__ float g_m[NN * HH];
__device__ float g_inv[NN * HH];
__device__ int g_deg[NN];
__device__ int g_off[NN + 1];
__device__ int g_cur[NN];
__device__ int g_src[EP];
__device__ int g_eid[EP];
__device__ int g_dst[EP];
__device__ int g_is64;

static cudaStream_t s_csr;
static cudaEvent_t ev_fork, ev_join, ev_l1, ev_fin;
static struct StreamInit {
    StreamInit() {
        cudaStreamCreateWithFlags(&s_csr, cudaStreamNonBlocking);
        cudaEventCreateWithFlags(&ev_fork, cudaEventDisableTiming);
        cudaEventCreateWithFlags(&ev_join, cudaEventDisableTiming);
        cudaEventCreateWithFlags(&ev_l1, cudaEventDisableTiming);
        cudaEventCreateWithFlags(&ev_fin, cudaEventDisableTiming);
    }
} s_init;

__device__ __forceinline__ int edge_at(const void* ei, int idx) {
    if (g_is64) return (int)((const long long*)ei)[idx];
    return ((const int*)ei)[idx];
}

__global__ void detect_dtype(const unsigned int* __restrict__ ei) {
    int t = threadIdx.x;
    int bad = (ei[2 * t + 1] != 0u) || (ei[2 * t] >= (unsigned)NN);
    int nbad = __syncthreads_count(bad);
    if (t == 0) g_is64 = (nbad == 0) ? 1 : 0;
}

__global__ void init_deg() {
    int i = blockIdx.x * blockDim.x + threadIdx.x;
    if (i < NN) g_deg[i] = 1;
}

__global__ void count_deg(const void* __restrict__ ei) {
    int e = blockIdx.x * blockDim.x + threadIdx.x;
    if (e < EE) atomicAdd(&g_deg[edge_at(ei, EE + e)], 1);
}

__global__ void scan_off() {
    __shared__ int ss[1024];
    int t = threadIdx.x;
    const int CH = (NN + 1023) / 1024;
    int base = t * CH;
    int s = 0;
    for (int i = 0; i < CH; i++) {
        int idx = base + i;
        if (idx < NN) s += g_deg[idx];
    }
    ss[t] = s;
    __syncthreads();
    for (int o = 1; o < 1024; o <<= 1) {
        int v = (t >= o) ? ss[t - o] : 0;
        __syncthreads();
        ss[t] += v;
        __syncthreads();
    }
    int run = (t == 0) ? 0 : ss[t - 1];
    for (int i = 0; i < CH; i++) {
        int idx = base + i;
        if (idx < NN) {
            g_off[idx] = run;
            g_cur[idx] = run;
            run += g_deg[idx];
        }
    }
    if (t == 1023) g_off[NN] = ss[1023];
}

__global__ void fill_csr(const void* __restrict__ ei) {
    int e = blockIdx.x * blockDim.x + threadIdx.x;
    if (e >= EP) return;
    int s, d;
    if (e < EE) {
        s = edge_at(ei, e);
        d = edge_at(ei, EE + e);
    } else {
        s = e - EE;
        d = s;
    }
    int pos = atomicAdd(&g_cur[d], 1);
    g_src[pos] = s;
    g_eid[pos] = e;
    g_dst[pos] = d;
}

__global__ void finalize_alpha(float* __restrict__ alpha) {
    int e = blockIdx.x * blockDim.x + threadIdx.x;
    if (e >= EP) return;
    float4 lg = *(const float4*)(g_scr + (size_t)e * HH);
    int d = g_dst[e];
    float4 m4 = *(const float4*)(g_m + (size_t)d * HH);
    float4 i4 = *(const float4*)(g_inv + (size_t)d * HH);
    float4 av;
    av.x = __expf(lg.x - m4.x) * i4.x;
    av.y = __expf(lg.y - m4.y) * i4.y;
    av.z = __expf(lg.z - m4.z) * i4.z;
    av.w = __expf(lg.w - m4.w) * i4.w;
    *(float4*)(alpha + (size_t)g_eid[e] * HH) = av;
}

// ---------------- 3xTF32 tensor-core GEMM, double-buffered ----------------
__device__ __forceinline__ unsigned tf32_of(float v) {
    unsigned r;
    asm("cvt.rna.tf32.f32 %0, %1;" : "=r"(r) : "f"(v));
    return r;
}

__device__ __forceinline__ void mma8(float* d, const unsigned* a, const unsigned* b) {
    asm volatile(
        "mma.sync.aligned.m16n8k8.row.col.f32.tf32.tf32.f32 "
        "{%0,%1,%2,%3}, {%4,%5,%6,%7}, {%8,%9}, {%0,%1,%2,%3};"
        : "+f"(d[0]), "+f"(d[1]), "+f"(d[2]), "+f"(d[3])
        : "r"(a[0]), "r"(a[1]), "r"(a[2]), "r"(a[3]), "r"(b[0]), "r"(b[1]));
}

template <int ASEL, int K>
__global__ void __launch_bounds__(256) gemm_tf32(const float* __restrict__ Aext,
                                                 const float* __restrict__ B0,
                                                 const float* __restrict__ B1) {
    const float* A = (ASEL == 0) ? Aext : (const float*)g_h;

    extern __shared__ float dsm[];
    float* AsH = dsm;                      // [2][16][ASTR]
    float* AsL = AsH + 2 * A_BUF;
    float* BsH = AsL + 2 * A_BUF;          // [2][2][16][BSTR]  (buf, z, k, n)
    float* BsL = BsH + 2 * B_BUF;

#define ASHI(b, k, m) AsH[((b) * 16 + (k)) * ASTR + (m)]
#define ASLO(b, k, m) AsL[((b) * 16 + (k)) * ASTR + (m)]
#define BSHI(b, z, k, n) BsH[(((b) * 2 + (z)) * 16 + (k)) * BSTR + (n)]
#define BSLO(b, z, k, n) BsL[(((b) * 2 + (z)) * 16 + (k)) * BSTR + (n)]

    int t = threadIdx.x;
    int lane = t & 31, wid = t >> 5;
    int wm = wid & 3, wn = wid >> 2;
    int tg = lane >> 2, tq = lane & 3;
    int bm = blockIdx.y * 128, bn = blockIdx.x * 64;

    float acc[2][2][4][4];
#pragma unroll
    for (int z = 0; z < 2; z++)
#pragma unroll
        for (int mt = 0; mt < 2; mt++)
#pragma unroll
            for (int nt = 0; nt < 4; nt++)
#pragma unroll
                for (int j = 0; j < 4; j++) acc[z][mt][nt][j] = 0.f;

    const int ar0 = t >> 2, ac0 = (t & 3) * 4;
    const int ar1 = (t + 256) >> 2;
    const int br = t >> 4, bc = (t & 15) * 4;

    // prefetch tile 0 into regs
    float4 avA0 = make_float4(0.f, 0.f, 0.f, 0.f);
    float4 avA1 = make_float4(0.f, 0.f, 0.f, 0.f);
    float4 bv0, bv1;
    if (bm + ar0 < NN) avA0 = *(const float4*)(A + (size_t)(bm + ar0) * K + ac0);
    if (bm + ar1 < NN) avA1 = *(const float4*)(A + (size_t)(bm + ar1) * K + ac0);
    bv0 = *(const float4*)(B0 + (size_t)br * HC + bn + bc);
    bv1 = *(const float4*)(B1 + (size_t)br * HC + bn + bc);

    const int NT = K / 16;
    for (int it = 0; it < NT; it++) {
        int buf = it & 1;
        // ---- store current tile regs -> buf ----
        {
            float vv0[4] = {avA0.x, avA0.y, avA0.z, avA0.w};
            float vv1[4] = {avA1.x, avA1.y, avA1.z, avA1.w};
#pragma unroll
            for (int j = 0; j < 4; j++) {
                unsigned hi = tf32_of(vv0[j]);
                float hif = __uint_as_float(hi);
                unsigned lo = tf32_of(vv0[j] - hif);
                ASHI(buf, ac0 + j, ar0) = hif;
                ASLO(buf, ac0 + j, ar0) = __uint_as_float(lo);
                hi = tf32_of(vv1[j]);
                hif = __uint_as_float(hi);
                lo = tf32_of(vv1[j] - hif);
                ASHI(buf, ac0 + j, ar1) = hif;
                ASLO(buf, ac0 + j, ar1) = __uint_as_float(lo);
            }
            float bb0[4] = {bv0.x, bv0.y, bv0.z, bv0.w};
            float bb1[4] = {bv1.x, bv1.y, bv1.z, bv1.w};
#pragma unroll
            for (int j = 0; j < 4; j++) {
                unsigned hi = tf32_of(bb0[j]);
                float hif = __uint_as_float(hi);
                unsigned lo = tf32_of(bb0[j] - hif);
                BSHI(buf, 0, br, bc + j) = hif;
                BSLO(buf, 0, br, bc + j) = __uint_as_float(lo);
                hi = tf32_of(bb1[j]);
                hif = __uint_as_float(hi);
                lo = tf32_of(bb1[j] - hif);
                BSHI(buf, 1, br, bc + j) = hif;
                BSLO(buf, 1, br, bc + j) = __uint_as_float(lo);
            }
        }
        __syncthreads();   // single barrier per k-tile

        // ---- prefetch next tile (latency hidden under mma) ----
        if (it + 1 < NT) {
            int kn = (it + 1) * 16;
            avA0 = make_float4(0.f, 0.f, 0.f, 0.f);
            avA1 = make_float4(0.f, 0.f, 0.f, 0.f);
            if (bm + ar0 < NN) avA0 = *(const float4*)(A + (size_t)(bm + ar0) * K + kn + ac0);
            if (bm + ar1 < NN) avA1 = *(const float4*)(A + (size_t)(bm + ar1) * K + kn + ac0);
            bv0 = *(const float4*)(B0 + (size_t)(kn + br) * HC + bn + bc);
            bv1 = *(const float4*)(B1 + (size_t)(kn + br) * HC + bn + bc);
        }

        // ---- mma on buf ----
#pragma unroll
        for (int ks = 0; ks < 2; ks++) {
            int kk = ks * 8;
            unsigned ah[2][4], al[2][4];
#pragma unroll
            for (int mt = 0; mt < 2; mt++) {
                int rb = wm * 32 + mt * 16;
                ah[mt][0] = __float_as_uint(ASHI(buf, kk + tq, rb + tg));
                ah[mt][1] = __float_as_uint(ASHI(buf, kk + tq, rb + tg + 8));
                ah[mt][2] = __float_as_uint(ASHI(buf, kk + tq + 4, rb + tg));
                ah[mt][3] = __float_as_uint(ASHI(buf, kk + tq + 4, rb + tg + 8));
                al[mt][0] = __float_as_uint(ASLO(buf, kk + tq, rb + tg));
                al[mt][1] = __float_as_uint(ASLO(buf, kk + tq, rb + tg + 8));
                al[mt][2] = __float_as_uint(ASLO(buf, kk + tq + 4, rb + tg));
                al[mt][3] = __float_as_uint(ASLO(buf, kk + tq + 4, rb + tg + 8));
            }
#pragma unroll
            for (int z = 0; z < 2; z++) {
#pragma unroll
                for (int nt = 0; nt < 4; nt++) {
                    int cb = wn * 32 + nt * 8;
                    unsigned bh[2], bl[2];
                    bh[0] = __float_as_uint(BSHI(buf, z, kk + tq, cb + tg));
                    bh[1] = __float_as_uint(BSHI(buf, z, kk + tq + 4, cb + tg));
                    bl[0] = __float_as_uint(BSLO(buf, z, kk + tq, cb + tg));
                    bl[1] = __float_as_uint(BSLO(buf, z, kk + tq + 4, cb + tg));
#pragma unroll
                    for (int mt = 0; mt < 2; mt++) {
                        mma8(acc[z][mt][nt], ah[mt], bh);
                        mma8(acc[z][mt][nt], ah[mt], bl);
                        mma8(acc[z][mt][nt], al[mt], bh);
                    }
                }
            }
        }
        // no trailing barrier: next iter writes the other buffer
    }

#pragma unroll
    for (int z = 0; z < 2; z++) {
        float* C = z ? g_xr : g_xl;
#pragma unroll
        for (int mt = 0; mt < 2; mt++)
#pragma unroll
            for (int nt = 0; nt < 4; nt++) {
                int row = bm + wm * 32 + mt * 16 + tg;
                int col = bn + wn * 32 + nt * 8 + 2 * tq;
                if (row < NN)
                    *(float2*)(C + (size_t)row * HC + col) =
                        make_float2(acc[z][mt][nt][0], acc[z][mt][nt][1]);
                if (row + 8 < NN)
                    *(float2*)(C + (size_t)(row + 8) * HC + col) =
                        make_float2(acc[z][mt][nt][2], acc[z][mt][nt][3]);
            }
    }
#undef ASHI
#undef ASLO
#undef BSHI
#undef BSLO
}

// ---------------- edge / softmax / aggregate kernel ----------------
template <int LAYER, int FIN>
__global__ void __launch_bounds__(128) edge_attn(
    const float* __restrict__ att, const float* __restrict__ bias,
    const float* __restrict__ bng, const float* __restrict__ bnb,
    const float* __restrict__ bnm, const float* __restrict__ bnv,
    const float* __restrict__ Wlin, const float* __restrict__ blin,
    float* __restrict__ alpha, float* __restrict__ nodeout) {
    const float* xl = (const float*)g_xl;
    const float* xr = (const float*)g_xr;
    int i = blockIdx.x, t = threadIdx.x;
    int h = t >> 5, lane = t & 31;
    int start = g_off[i], end = g_off[i + 1];
    int col = h * CC + lane * 4;

    const float4 xr4 = *(const float4*)(xr + (size_t)i * HC + col);
    const float4 a4 = *(const float4*)(att + col);

    float m = -3.4e38f, denom = 0.f;
    float4 acc = make_float4(0.f, 0.f, 0.f, 0.f);

    int e = start;
    int deg = end - start;
    int nfull = deg & ~(EILP - 1);

    for (; e < start + nfull; e += EILP) {
        int s[EILP];
        float4 xv[EILP];
#pragma unroll
        for (int j = 0; j < EILP; j++) s[j] = g_src[e + j];
#pragma unroll
        for (int j = 0; j < EILP; j++)
            xv[j] = *(const float4*)(xl + (size_t)s[j] * HC + col);

        float p[EILP];
#pragma unroll
        for (int j = 0; j < EILP; j++) {
            float t0 = xv[j].x + xr4.x;
            float t1 = xv[j].y + xr4.y;
            float t2 = xv[j].z + xr4.z;
            float t3 = xv[j].w + xr4.w;
            t0 = t0 > 0.f ? t0 : 0.2f * t0;
            t1 = t1 > 0.f ? t1 : 0.2f * t1;
            t2 = t2 > 0.f ? t2 : 0.2f * t2;
            t3 = t3 > 0.f ? t3 : 0.2f * t3;
            p[j] = t0 * a4.x + t1 * a4.y + t2 * a4.z + t3 * a4.w;
        }
#pragma unroll
        for (int o = 16; o; o >>= 1) {
#pragma unroll
            for (int j = 0; j < EILP; j++)
                p[j] += __shfl_xor_sync(0xffffffffu, p[j], o);
        }
#pragma unroll
        for (int j = 0; j < EILP; j++) {
            if (lane == 0) g_scr[(e + j) * HH + h] = p[j];
            if (p[j] > m) {
                float sc = __expf(m - p[j]);
                denom *= sc;
                acc.x *= sc; acc.y *= sc; acc.z *= sc; acc.w *= sc;
                m = p[j];
            }
            float ex = __expf(p[j] - m);
            denom += ex;
            acc.x += ex * xv[j].x;
            acc.y += ex * xv[j].y;
            acc.z += ex * xv[j].z;
            acc.w += ex * xv[j].w;
        }
    }
    for (; e < end; e++) {
        int s = g_src[e];
        float4 xv = *(const float4*)(xl + (size_t)s * HC + col);
        float t0 = xv.x + xr4.x;
        float t1 = xv.y + xr4.y;
        float t2 = xv.z + xr4.z;
        float t3 = xv.w + xr4.w;
        t0 = t0 > 0.f ? t0 : 0.2f * t0;
        t1 = t1 > 0.f ? t1 : 0.2f * t1;
        t2 = t2 > 0.f ? t2 : 0.2f * t2;
        t3 = t3 > 0.f ? t3 : 0.2f * t3;
        float p = t0 * a4.x + t1 * a4.y + t2 * a4.z + t3 * a4.w;
#pragma unroll
        for (int o = 16; o; o >>= 1) p += __shfl_xor_sync(0xffffffffu, p, o);
        if (lane == 0) g_scr[e * HH + h] = p;
        if (p > m) {
            float sc = __expf(m - p);
            denom *= sc;
            acc.x *= sc; acc.y *= sc; acc.z *= sc; acc.w *= sc;
            m = p;
        }
        float ex = __expf(p - m);
        denom += ex;
        acc.x += ex * xv.x;
        acc.y += ex * xv.y;
        acc.z += ex * xv.z;
        acc.w += ex * xv.w;
    }
    float inv = 1.f / (denom + 1e-16f);

    __shared__ float red[HC];
    __shared__ float sm_m[HH], sm_inv[HH];
    red[col + 0] = acc.x * inv;
    red[col + 1] = acc.y * inv;
    red[col + 2] = acc.z * inv;
    red[col + 3] = acc.w * inv;
    if (lane == 0) {
        if (FIN) {
            sm_m[h] = m;
            sm_inv[h] = inv;
        } else {
            g_m[i * HH + h] = m;
            g_inv[i * HH + h] = inv;
        }
    }
    __syncthreads();

    if (FIN) {
        for (int ee = start + t; ee < end; ee += 128) {
            float4 lg = *(const float4*)(g_scr + ee * HH);
            float4 av;
            av.x = __expf(lg.x - sm_m[0]) * sm_inv[0];
            av.y = __expf(lg.y - sm_m[1]) * sm_inv[1];
            av.z = __expf(lg.z - sm_m[2]) * sm_inv[2];
            av.w = __expf(lg.w - sm_m[3]) * sm_inv[3];
            *(float4*)(alpha + (size_t)g_eid[ee] * HH) = av;
        }
    }

    float sum = (red[t] + red[CC + t] + red[2 * CC + t] + red[3 * CC + t]) * 0.25f + bias[t];
    float scale = bng[t] * rsqrtf(bnv[t] + 1e-5f);
    float y = (sum - bnm[t]) * scale + bnb[t];
    y = fmaxf(y, 0.f);

    if (LAYER == 1) {
        g_h[(size_t)i * CC + t] = y;
    } else {
        __shared__ float rr[CC];
        rr[t] = y * Wlin[t];
        __syncthreads();
#pragma unroll
        for (int o = 64; o; o >>= 1) {
            if (t < o) rr[t] += rr[t + o];
            __syncthreads();
        }
        if (t == 0) {
            float z = fmaxf(rr[0] + blin[0], 0.f);
            nodeout[i] = 1.f / (1.f + __expf(-z));
        }
    }
}

// ---------------- launch ----------------
extern "C" void kernel_launch(void* const* d_in, const int* in_sizes, int n_in,
                              void* d_out, int out_size) {
    const float* x = (const float*)d_in[0];
    const void* ei = d_in[1];
    const float* Wl1 = (const float*)d_in[2];
    const float* Wr1 = (const float*)d_in[3];
    const float* att1 = (const float*)d_in[4];
    const float* b1 = (const float*)d_in[5];
    const float* Wl2 = (const float*)d_in[6];
    const float* Wr2 = (const float*)d_in[7];
    const float* att2 = (const float*)d_in[8];
    const float* b2 = (const float*)d_in[9];
    const float* g1 = (const float*)d_in[10];
    const float* be1 = (const float*)d_in[11];
    const float* m1 = (const float*)d_in[12];
    const float* v1 = (const float*)d_in[13];
    const float* g2 = (const float*)d_in[14];
    const float* be2 = (const float*)d_in[15];
    const float* m2 = (const float*)d_in[16];
    const float* v2 = (const float*)d_in[17];
    const float* Wlin = (const float*)d_in[18];
    const float* blin = (const float*)d_in[19];

    float* out = (float*)d_out;
    float* alpha1 = out + NN;
    float* alpha2 = alpha1 + (size_t)EP * HH;

    // raise dynamic smem cap (host attribute set; idempotent, capture-safe)
    static bool attr_done = false;
    if (!attr_done) {
        cudaFuncSetAttribute(gemm_tf32<0, INC>,
                             cudaFuncAttributeMaxDynamicSharedMemorySize, SMEM_BYTES);
        cudaFuncSetAttribute(gemm_tf32<1, CC>,
                             cudaFuncAttributeMaxDynamicSharedMemorySize, SMEM_BYTES);
        attr_done = true;
    }

    cudaEventRecord(ev_fork, 0);
    cudaStreamWaitEvent(s_csr, ev_fork, 0);
    detect_dtype<<<1, 128, 0, s_csr>>>((const unsigned int*)ei);
    init_deg<<<(NN + 255) / 256, 256, 0, s_csr>>>();
    count_deg<<<(EE + 255) / 256, 256, 0, s_csr>>>(ei);

    dim3 gg(HC / 64, (NN + 127) / 128);
    gemm_tf32<0, INC><<<gg, 256, SMEM_BYTES>>>(x, Wl1, Wr1);

    scan_off<<<1, 1024, 0, s_csr>>>();
    fill_csr<<<(EP + 255) / 256, 256, 0, s_csr>>>(ei);
    cudaEventRecord(ev_join, s_csr);

    cudaStreamWaitEvent(0, ev_join, 0);
    edge_attn<1, 0><<<NN, 128>>>(att1, b1, g1, be1, m1, v1,
                                 nullptr, nullptr, alpha1, nullptr);
    cudaEventRecord(ev_l1, 0);

    cudaStreamWaitEvent(s_csr, ev_l1, 0);
    finalize_alpha<<<(EP + 255) / 256, 256, 0, s_csr>>>(alpha1);
    cudaEventRecord(ev_fin, s_csr);

    gemm_tf32<1, CC><<<gg, 256, SMEM_BYTES>>>(nullptr, Wl2, Wr2);

    cudaStreamWaitEvent(0, ev_fin, 0);
    edge_attn<2, 1><<<NN, 128>>>(att2, b2, g2, be2, m2, v2,
                                 Wlin, blin, alpha2, out);
}